// round 15
// baseline (speedup 1.0000x reference)
#include <cuda_runtime.h>
#include <cuda_fp16.h>
#include <cstdint>
#include <cstddef>

// Problem constants
#define BB 2
#define SS 2048
#define DD 1024
#define HH 16
#define HDIM 64
#define MLPD 4096
#define NROWS (BB * SS)   // 4096

// ---------------------------------------------------------------------------
// Scratch (device globals) — all activations fp16
// ---------------------------------------------------------------------------
__device__ __half g_h1[NROWS * DD];
__device__ __half g_qb[NROWS * DD];
__device__ __half g_kb[NROWS * DD];
__device__ __half g_vb[NROWS * DD];
__device__ float  g_att[NROWS * DD];
__device__ float  g_ln2[NROWS * DD];
__device__ __half g_ln2h[NROWS * DD];
__device__ __half g_mlp[NROWS * MLPD];
__device__ __half g_msum[(size_t)BB * SS * SS];          // dis+cls, fp16
__device__ __half g_wqkvT[3 * DD * DD];
__device__ __half g_w1T[DD * MLPD];
__device__ __half g_w2T[DD * MLPD];
__device__ float  g_bqkv[3 * DD];

// ---------------------------------------------------------------------------
// PTX helpers
// ---------------------------------------------------------------------------
__device__ __forceinline__ uint32_t smem_u32(const void* p) {
    return (uint32_t)__cvta_generic_to_shared(p);
}
__device__ __forceinline__ void ldsm4(uint32_t* r, uint32_t a) {
    asm volatile("ldmatrix.sync.aligned.m8n8.x4.shared.b16 {%0,%1,%2,%3}, [%4];"
                 : "=r"(r[0]), "=r"(r[1]), "=r"(r[2]), "=r"(r[3]) : "r"(a));
}
__device__ __forceinline__ void ldsm4t(uint32_t* r, uint32_t a) {
    asm volatile("ldmatrix.sync.aligned.m8n8.x4.trans.shared.b16 {%0,%1,%2,%3}, [%4];"
                 : "=r"(r[0]), "=r"(r[1]), "=r"(r[2]), "=r"(r[3]) : "r"(a));
}
__device__ __forceinline__ void mma16816(float* c, const uint32_t* a, const uint32_t* b) {
    asm volatile("mma.sync.aligned.m16n8k16.row.col.f32.f16.f16.f32 "
                 "{%0,%1,%2,%3}, {%4,%5,%6,%7}, {%8,%9}, {%0,%1,%2,%3};"
                 : "+f"(c[0]), "+f"(c[1]), "+f"(c[2]), "+f"(c[3])
                 : "r"(a[0]), "r"(a[1]), "r"(a[2]), "r"(a[3]), "r"(b[0]), "r"(b[1]));
}
__device__ __forceinline__ void cp16(uint32_t d, const void* s) {
    asm volatile("cp.async.cg.shared.global [%0], [%1], 16;" :: "r"(d), "l"(s) : "memory");
}
__device__ __forceinline__ void cp_commit() {
    asm volatile("cp.async.commit_group;" ::: "memory");
}
template <int N>
__device__ __forceinline__ void cpwait() {
    asm volatile("cp.async.wait_group %0;" :: "n"(N) : "memory");
}
__device__ __forceinline__ uint32_t packhf(float lo, float hi) {
    uint32_t d;
    asm("cvt.rn.f16x2.f32 %0, %1, %2;" : "=r"(d) : "f"(hi), "f"(lo));
    return d;
}
__device__ __forceinline__ float gelu_exact(float x) {
    return 0.5f * x * (1.0f + erff(x * 0.70710678118654752f));
}

// ---------------------------------------------------------------------------
// Block LayerNorm, ONE barrier: warp partials -> smem -> barrier ->
// every thread redundantly sums the 8 partials (broadcast LDS, no 2nd sync).
// ---------------------------------------------------------------------------
__device__ __forceinline__ void ln_body(const float* __restrict__ in,
                                        const float* __restrict__ res,
                                        const float* __restrict__ gam,
                                        const float* __restrict__ bet,
                                        float* __restrict__ outf, __half* __restrict__ oh,
                                        int row, int t)
{
    float4 v = ((const float4*)(in + (size_t)row * DD))[t];
    if (res) {
        float4 r = ((const float4*)(res + (size_t)row * DD))[t];
        v.x += r.x; v.y += r.y; v.z += r.z; v.w += r.w;
    }
    float s  = v.x + v.y + v.z + v.w;
    float sq = v.x*v.x + v.y*v.y + v.z*v.z + v.w*v.w;

    __shared__ float red[16];
    #pragma unroll
    for (int o = 16; o; o >>= 1) {
        s  += __shfl_xor_sync(0xffffffffu, s,  o);
        sq += __shfl_xor_sync(0xffffffffu, sq, o);
    }
    int w = t >> 5, lane = t & 31;
    if (lane == 0) { red[w] = s; red[8 + w] = sq; }
    __syncthreads();
    float ts = 0.f, tq = 0.f;
    #pragma unroll
    for (int i = 0; i < 8; i++) { ts += red[i]; tq += red[8 + i]; }

    float mu  = ts * (1.0f / DD);
    float var = tq * (1.0f / DD) - mu * mu;
    float rn  = rsqrtf(var + 1e-5f);

    float4 g = ((const float4*)gam)[t];
    float4 b = ((const float4*)bet)[t];
    float o0 = (v.x - mu) * rn * g.x + b.x;
    float o1 = (v.y - mu) * rn * g.y + b.y;
    float o2 = (v.z - mu) * rn * g.z + b.z;
    float o3 = (v.w - mu) * rn * g.w + b.w;

    size_t base = (size_t)row * DD + t * 4;
    if (outf) *(float4*)(outf + base) = make_float4(o0, o1, o2, o3);
    *(__half2*)(oh + base)     = __floats2half2_rn(o0, o1);
    *(__half2*)(oh + base + 2) = __floats2half2_rn(o2, o3);
}

// LN2: residual + LN -> f32 + fp16 (one row per 256-thread block)
__global__ void ln_kernel(const float* __restrict__ in, const float* __restrict__ res,
                          const float* __restrict__ gam, const float* __restrict__ bet,
                          float* __restrict__ outf, __half* __restrict__ oh)
{
    ln_body(in, res, gam, bet, outf, oh, blockIdx.x, threadIdx.x);
}

// ---------------------------------------------------------------------------
// Fused preprocessing: one launch, block-range dispatch.
//   [0,      8192) : msum = fp16(dis + cls)
//   [8192,  11264) : wq/wk/wv transpose->fp16 + bias concat
//   [11264, 15360) : w1 transpose
//   [15360, 19456) : w2 transpose
//   [19456, 23552) : LN1 (block per row)
// ---------------------------------------------------------------------------
#define PRE_MSUM_END   8192
#define PRE_QKV_END    11264
#define PRE_W1_END     15360
#define PRE_W2_END     19456
#define PRE_TOTAL      23552

__device__ __forceinline__ void ttrans_body(const float* __restrict__ W,
                                            __half* __restrict__ o,
                                            int K, int N, int bx, int by,
                                            int tx, int ty)
{
    __shared__ float tile[32][33];
    int n0 = bx * 32, k0 = by * 32;
    #pragma unroll
    for (int i = 0; i < 32; i += 8)
        tile[ty + i][tx] = W[(size_t)(k0 + ty + i) * N + n0 + tx];
    __syncthreads();
    #pragma unroll
    for (int i = 0; i < 32; i += 8)
        o[(size_t)(n0 + ty + i) * K + k0 + tx] = __float2half_rn(tile[tx][ty + i]);
}

__global__ void preproc_kernel(
    const float* __restrict__ dis, const float* __restrict__ cls,
    __half* __restrict__ msum,
    const float* __restrict__ wq, const float* __restrict__ wk,
    const float* __restrict__ wv,
    const float* __restrict__ bq, const float* __restrict__ bk,
    const float* __restrict__ bv,
    __half* __restrict__ wqkvT, float* __restrict__ bqkv,
    const float* __restrict__ w1, __half* __restrict__ w1T,
    const float* __restrict__ w2, __half* __restrict__ w2T,
    const float* __restrict__ x,
    const float* __restrict__ ln1g, const float* __restrict__ ln1b,
    __half* __restrict__ h1)
{
    int bid = blockIdx.x;
    int t = threadIdx.x;
    int tx = t & 31, ty = t >> 5;

    if (bid < PRE_MSUM_END) {
        size_t i = ((size_t)bid * 256 + t) * 4;
        float4 d = *(const float4*)(dis + i);
        float4 c = *(const float4*)(cls + i);
        *(__half2*)(msum + i)     = __floats2half2_rn(d.x + c.x, d.y + c.y);
        *(__half2*)(msum + i + 2) = __floats2half2_rn(d.z + c.z, d.w + c.w);
    } else if (bid < PRE_QKV_END) {
        int r = bid - PRE_MSUM_END;
        int z = r >> 10;           // 0..2
        r &= 1023;
        int bx = r & 31, by = r >> 5;
        const float* W = (z == 0) ? wq : (z == 1) ? wk : wv;
        ttrans_body(W, wqkvT + (size_t)z * DD * DD, DD, DD, bx, by, tx, ty);
        if (bx == 0 && by == 0) {
            const float* bsrc = (z == 0) ? bq : (z == 1) ? bk : bv;
            #pragma unroll
            for (int i = t; i < DD; i += 256) bqkv[z * DD + i] = bsrc[i];
        }
    } else if (bid < PRE_W1_END) {
        int r = bid - PRE_QKV_END;
        int bx = r & 127, by = r >> 7;     // grid (128, 32)
        ttrans_body(w1, w1T, DD, MLPD, bx, by, tx, ty);
    } else if (bid < PRE_W2_END) {
        int r = bid - PRE_W1_END;
        int bx = r & 31, by = r >> 5;      // grid (32, 128)
        ttrans_body(w2, w2T, MLPD, DD, bx, by, tx, ty);
    } else {
        int row = bid - PRE_W2_END;
        ln_body(x, nullptr, ln1g, ln1b, nullptr, h1, row, t);
    }
}

// ---------------------------------------------------------------------------
// fp16 mma.sync GEMM, 128 threads, 4 warps of 64x64 warp tiles.
// Tile 128x128 x BK=64, 3-stage cp.async, one barrier per chunk, 2 CTAs/SM.
// EPI: 0 = bias -> fp16 routed to q/k/v;  1 = bias+GELU -> fp16;
//      2 = bias + f32 residual -> f32
// ---------------------------------------------------------------------------
#define GTILE 18432            // 128 rows * 144B
#define GSTAGE (2 * GTILE)     // A, B
#define GEMM_SMEM (3 * GSTAGE) // 110592

template <int EPI>
__global__ void __launch_bounds__(128, 2) gemm_mma(
    const __half* __restrict__ A, int lda,
    const __half* __restrict__ B,
    const float* __restrict__ bias, const float* __restrict__ addsrc,
    float* __restrict__ Cf,
    __half* __restrict__ Cbq, __half* __restrict__ Cbk, __half* __restrict__ Cbv,
    __half* __restrict__ Ch,
    int M, int N, int K)
{
    extern __shared__ __align__(128) char smem[];
    uint32_t sb = smem_u32(smem);
    int t = threadIdx.x, lane = t & 31, wid = t >> 5;
    int wm = wid & 1, wn = wid >> 1;          // 2x2 warps, warp tile 64x64
    int brow = blockIdx.y * 128, bcol = blockIdx.x * 128;

    const __half* Ab = A + (size_t)brow * lda;
    const __half* Bb = B + (size_t)bcol * K;
    const int NC = K / 64;

    auto load_chunk = [&](int c, int stg) {
        int k0 = c * 64;
        uint32_t sbase = sb + stg * GSTAGE;
        #pragma unroll
        for (int i = 0; i < 16; i++) {
            int cid = t + i * 128;
            int tile = cid >> 10;             // 0=A 1=B
            int w = cid & 1023;
            int row = w >> 3, g = w & 7;
            const __half* src = (tile ? Bb + (size_t)row * K : Ab + (size_t)row * lda)
                                + k0 + g * 8;
            cp16(sbase + tile * GTILE + row * 144 + g * 16, src);
        }
    };

    float acc[4][8][4];
    #pragma unroll
    for (int i = 0; i < 4; i++)
        #pragma unroll
        for (int j = 0; j < 8; j++)
            #pragma unroll
            for (int q = 0; q < 4; q++) acc[i][j][q] = 0.f;

    load_chunk(0, 0); cp_commit();
    load_chunk(1, 1); cp_commit();

    for (int c = 0; c < NC; c++) {
        if (c + 1 < NC) cpwait<1>(); else cpwait<0>();
        __syncthreads();
        if (c + 2 < NC) { load_chunk(c + 2, (c + 2) % 3); cp_commit(); }

        uint32_t stg = sb + (c % 3) * GSTAGE;
        #pragma unroll
        for (int hb = 0; hb < 2; hb++) {
            uint32_t kb2 = hb * 64;
            uint32_t ah[8][4];                // 4 row-groups x 2 ks
            #pragma unroll
            for (int it = 0; it < 4; it++)
                #pragma unroll
                for (int ks = 0; ks < 2; ks++) {
                    int row = wm * 64 + it * 16 + (lane & 15);
                    ldsm4(ah[it * 2 + ks],
                          stg + (uint32_t)(row * 144) + kb2 + ks * 32 + (lane >> 4) * 16);
                }
            #pragma unroll
            for (int g2 = 0; g2 < 2; g2++) {
                uint32_t bq[4][4];
                #pragma unroll
                for (int n4 = 0; n4 < 4; n4++) {
                    int n = wn * 64 + (g2 * 4 + n4) * 8 + (lane & 7);
                    ldsm4(bq[n4], stg + GTILE + (uint32_t)(n * 144) + kb2 + (lane >> 3) * 16);
                }
                #pragma unroll
                for (int it = 0; it < 4; it++)
                    #pragma unroll
                    for (int ks = 0; ks < 2; ks++)
                        #pragma unroll
                        for (int n4 = 0; n4 < 4; n4++)
                            mma16816(acc[it][g2 * 4 + n4],
                                     ah[it * 2 + ks], &bq[n4][ks * 2]);
            }
        }
    }

    // ---- epilogue ----
    __half* Cb = Cbq;
    int colbase = bcol;
    if (EPI == 0) {
        int which = bcol >> 10;
        Cb = (which == 0) ? Cbq : (which == 1) ? Cbk : Cbv;
        colbase = bcol & 1023;
    }
    const int OSTR = (EPI == 0) ? DD : N;

    #pragma unroll
    for (int it = 0; it < 4; it++) {
        int r0 = brow + wm * 64 + it * 16 + (lane >> 2);
        #pragma unroll
        for (int nt = 0; nt < 8; nt++) {
            int cofs = wn * 64 + nt * 8 + 2 * (lane & 3);
            int gb = bcol + cofs;
            int col = colbase + cofs;
            float b0 = bias[gb], b1 = bias[gb + 1];
            float v00 = acc[it][nt][0] + b0, v01 = acc[it][nt][1] + b1;
            float v10 = acc[it][nt][2] + b0, v11 = acc[it][nt][3] + b1;
            if (EPI == 0) {
                *(uint32_t*)(Cb + (size_t)r0 * OSTR + col)       = packhf(v00, v01);
                *(uint32_t*)(Cb + (size_t)(r0 + 8) * OSTR + col) = packhf(v10, v11);
            } else if (EPI == 1) {
                v00 = gelu_exact(v00); v01 = gelu_exact(v01);
                v10 = gelu_exact(v10); v11 = gelu_exact(v11);
                *(uint32_t*)(Ch + (size_t)r0 * OSTR + col)       = packhf(v00, v01);
                *(uint32_t*)(Ch + (size_t)(r0 + 8) * OSTR + col) = packhf(v10, v11);
            } else {
                const float* a0 = addsrc + (size_t)r0 * OSTR + col;
                const float* a1 = addsrc + (size_t)(r0 + 8) * OSTR + col;
                *(float2*)(Cf + (size_t)r0 * OSTR + col)       = make_float2(v00 + a0[0], v01 + a0[1]);
                *(float2*)(Cf + (size_t)(r0 + 8) * OSTR + col) = make_float2(v10 + a1[0], v11 + a1[1]);
            }
        }
    }
}

// ---------------------------------------------------------------------------
// Flash attention WITHOUT online max (bounded scores). fp16 mma.sync,
// 128 threads / 4 warps x 32 q-rows, 3-stage K/V cp.async, fp16 fused mask.
// ---------------------------------------------------------------------------
#define ATT_Q 18432            // 128 x 144
#define ATT_KV 9216            // 64 x 144
#define ATT_SMEM (ATT_Q + 3 * 2 * ATT_KV)   // 73728

__global__ void __launch_bounds__(128, 2) attn_mma(
    const __half* __restrict__ q, const __half* __restrict__ k,
    const __half* __restrict__ v,
    const __half* __restrict__ msum,
    float* __restrict__ out)
{
    extern __shared__ __align__(128) char sm[];
    uint32_t sb = smem_u32(sm);

    int h = blockIdx.x, qi = blockIdx.y, b = blockIdx.z;
    int t = threadIdx.x, lane = t & 31, wid = t >> 5;
    int wr = wid * 32;          // warp owns rows wr..wr+31 (2 groups of 16)

    size_t base = (size_t)b * (SS * DD) + (size_t)h * (SS * HDIM);
    const __half* Qg = q + base + (size_t)qi * 128 * HDIM;
    const __half* Kg = k + base;
    const __half* Vg = v + base;

    // load Q tile (128 x 64 fp16)
    #pragma unroll
    for (int i = 0; i < 8; i++) {
        int cid = t + i * 128;
        int row = cid >> 3, g = cid & 7;
        *(uint4*)(sm + row * 144 + g * 16) = *(const uint4*)(Qg + row * 64 + g * 8);
    }

    auto load_kv = [&](int kb, int st) {
        uint32_t kbase = sb + ATT_Q + st * 2 * ATT_KV;
        #pragma unroll
        for (int i = 0; i < 8; i++) {
            int cid = t + i * 128;
            int tile = cid >> 9;              // 0=K 1=V
            int w2 = cid & 511;
            int row = w2 >> 3, g = w2 & 7;
            const __half* src = (tile ? Vg : Kg) + (size_t)(kb * 64 + row) * 64 + g * 8;
            cp16(kbase + tile * ATT_KV + row * 144 + g * 16, src);
        }
    };

    load_kv(0, 0); cp_commit();
    load_kv(1, 1); cp_commit();
    __syncthreads();   // Q visible

    uint32_t qf[2][4][4];
    #pragma unroll
    for (int rg = 0; rg < 2; rg++)
        #pragma unroll
        for (int kt = 0; kt < 4; kt++) {
            int row = wr + rg * 16 + (lane & 15);
            ldsm4(qf[rg][kt], sb + (uint32_t)(row * 144 + kt * 32 + (lane >> 4) * 16));
        }

    float o[2][8][4];
    #pragma unroll
    for (int rg = 0; rg < 2; rg++)
        #pragma unroll
        for (int nt = 0; nt < 8; nt++)
            #pragma unroll
            for (int j = 0; j < 4; j++) o[rg][nt][j] = 0.f;
    float lpart[2][2] = {{0.f, 0.f}, {0.f, 0.f}};   // per-lane partial row sums

    int r0 = qi * 128 + wr + (lane >> 2);
    const __half* msr = msum + ((size_t)b * SS + r0) * SS;
    const int NKB = SS / 64;

    for (int kb = 0; kb < NKB; kb++) {
        if (kb + 1 < NKB) cpwait<1>(); else cpwait<0>();
        __syncthreads();
        if (kb + 2 < NKB) { load_kv(kb + 2, (kb + 2) % 3); cp_commit(); }

        uint32_t sbK = sb + ATT_Q + (kb % 3) * 2 * ATT_KV;
        uint32_t sbV = sbK + ATT_KV;

        // QK^T for both row groups; K frags loaded once
        float s[2][8][4];
        #pragma unroll
        for (int rg = 0; rg < 2; rg++)
            #pragma unroll
            for (int nt = 0; nt < 8; nt++)
                s[rg][nt][0] = s[rg][nt][1] = s[rg][nt][2] = s[rg][nt][3] = 0.f;
        #pragma unroll
        for (int half_ = 0; half_ < 2; half_++) {
            uint32_t kfr[4][8];
            #pragma unroll
            for (int n4 = 0; n4 < 4; n4++) {
                int tok = (half_ * 4 + n4) * 8 + (lane & 7);
                ldsm4(kfr[n4],     sbK + (uint32_t)(tok * 144 + (lane >> 3) * 16));
                ldsm4(kfr[n4] + 4, sbK + (uint32_t)(tok * 144 + 64 + (lane >> 3) * 16));
            }
            #pragma unroll
            for (int kt = 0; kt < 4; kt++)
                #pragma unroll
                for (int n4 = 0; n4 < 4; n4++)
                    #pragma unroll
                    for (int rg = 0; rg < 2; rg++)
                        mma16816(s[rg][half_ * 4 + n4], qf[rg][kt], &kfr[n4][kt * 2]);
        }

        // scale + mask + exp (no max subtraction; bounded scores)
        int cbase = kb * 64 + 2 * (lane & 3);
        #pragma unroll
        for (int rg = 0; rg < 2; rg++) {
            const __half* mr = msr + (size_t)(rg * 16) * SS;
            #pragma unroll
            for (int nt = 0; nt < 8; nt++) {
                int c = cbase + nt * 8;
                float2 m0 = __half22float2(*(const __half2*)(mr + c));
                float2 m1 = __half22float2(*(const __half2*)(mr + 8 * SS + c));
                s[rg][nt][0] = __expf(s[rg][nt][0] * 0.125f + m0.x);
                s[rg][nt][1] = __expf(s[rg][nt][1] * 0.125f + m0.y);
                s[rg][nt][2] = __expf(s[rg][nt][2] * 0.125f + m1.x);
                s[rg][nt][3] = __expf(s[rg][nt][3] * 0.125f + m1.y);
                lpart[rg][0] += s[rg][nt][0] + s[rg][nt][1];
                lpart[rg][1] += s[rg][nt][2] + s[rg][nt][3];
            }
        }

        // pack P -> A frags (fp16), per row group
        uint32_t pf[2][4][4];
        #pragma unroll
        for (int rg = 0; rg < 2; rg++)
            #pragma unroll
            for (int kt2 = 0; kt2 < 4; kt2++) {
                int j0 = 2 * kt2, j1 = 2 * kt2 + 1;
                pf[rg][kt2][0] = packhf(s[rg][j0][0], s[rg][j0][1]);
                pf[rg][kt2][1] = packhf(s[rg][j0][2], s[rg][j0][3]);
                pf[rg][kt2][2] = packhf(s[rg][j1][0], s[rg][j1][1]);
                pf[rg][kt2][3] = packhf(s[rg][j1][2], s[rg][j1][3]);
            }

        // P @ V — V frags loaded once, used by both row groups; o never rescaled
        #pragma unroll
        for (int kt2 = 0; kt2 < 4; kt2++) {
            #pragma unroll
            for (int ntp = 0; ntp < 4; ntp++) {
                uint32_t vf[4];
                int tok = kt2 * 16 + (lane & 15);
                int hd = (2 * ntp + (lane >> 4)) * 8;
                ldsm4t(vf, sbV + (uint32_t)(tok * 144 + hd * 2));
                #pragma unroll
                for (int rg = 0; rg < 2; rg++) {
                    mma16816(o[rg][2 * ntp],     pf[rg][kt2], &vf[0]);
                    mma16816(o[rg][2 * ntp + 1], pf[rg][kt2], &vf[2]);
                }
            }
        }
    }

    // final l reduction (once): 4 lanes per row share quads
    float* Og = out + base + (size_t)qi * 128 * HDIM;
    #pragma unroll
    for (int rg = 0; rg < 2; rg++) {
        float l0 = lpart[rg][0], l1 = lpart[rg][1];
        l0 += __shfl_xor_sync(0xffffffffu, l0, 1);
        l0 += __shfl_xor_sync(0xffffffffu, l0, 2);
        l1 += __shfl_xor_sync(0xffffffffu, l1, 1);
        l1 += __shfl_xor_sync(0xffffffffu, l1, 2);
        float inv0 = 1.0f / l0, inv1 = 1.0f / l1;
        int lr = wr + rg * 16 + (lane >> 2);
        #pragma unroll
        for (int nt = 0; nt < 8; nt++) {
            int col = nt * 8 + 2 * (lane & 3);
            *(float2*)(Og + (size_t)lr * 64 + col) =
                make_float2(o[rg][nt][0] * inv0, o[rg][nt][1] * inv0);
            *(float2*)(Og + (size_t)(lr + 8) * 64 + col) =
                make_float2(o[rg][nt][2] * inv1, o[rg][nt][3] * inv1);
        }
    }
}

// ---------------------------------------------------------------------------
// Launch: 6 kernels total
// ---------------------------------------------------------------------------
extern "C" void kernel_launch(void* const* d_in, const int* in_sizes, int n_in,
                              void* d_out, int out_size)
{
    const float* x     = (const float*)d_in[0];
    const float* dis   = (const float*)d_in[1];
    const float* cls   = (const float*)d_in[2];
    const float* wq    = (const float*)d_in[3];
    const float* bq    = (const float*)d_in[4];
    const float* wk    = (const float*)d_in[5];
    const float* bk    = (const float*)d_in[6];
    const float* wv    = (const float*)d_in[7];
    const float* bv    = (const float*)d_in[8];
    const float* ln1g  = (const float*)d_in[9];
    const float* ln1b  = (const float*)d_in[10];
    const float* ln2g  = (const float*)d_in[11];
    const float* ln2b  = (const float*)d_in[12];
    const float* w1    = (const float*)d_in[13];
    const float* b1    = (const float*)d_in[14];
    const float* w2    = (const float*)d_in[15];
    const float* b2    = (const float*)d_in[16];
    float* out = (float*)d_out;

    __half *h1, *ln2h, *mlp, *qb, *kb, *vb, *wqkvT, *w1T, *w2T, *msum;
    float *att, *ln2o, *bqkv;
    cudaGetSymbolAddress((void**)&h1,    g_h1);
    cudaGetSymbolAddress((void**)&ln2h,  g_ln2h);
    cudaGetSymbolAddress((void**)&mlp,   g_mlp);
    cudaGetSymbolAddress((void**)&wqkvT, g_wqkvT);
    cudaGetSymbolAddress((void**)&w1T,   g_w1T);
    cudaGetSymbolAddress((void**)&w2T,   g_w2T);
    cudaGetSymbolAddress((void**)&qb,    g_qb);
    cudaGetSymbolAddress((void**)&kb,    g_kb);
    cudaGetSymbolAddress((void**)&vb,    g_vb);
    cudaGetSymbolAddress((void**)&att,   g_att);
    cudaGetSymbolAddress((void**)&ln2o,  g_ln2);
    cudaGetSymbolAddress((void**)&bqkv,  g_bqkv);
    cudaGetSymbolAddress((void**)&msum,  g_msum);

    cudaFuncSetAttribute(gemm_mma<0>, cudaFuncAttributeMaxDynamicSharedMemorySize, GEMM_SMEM);
    cudaFuncSetAttribute(gemm_mma<1>, cudaFuncAttributeMaxDynamicSharedMemorySize, GEMM_SMEM);
    cudaFuncSetAttribute(gemm_mma<2>, cudaFuncAttributeMaxDynamicSharedMemorySize, GEMM_SMEM);
    cudaFuncSetAttribute(attn_mma, cudaFuncAttributeMaxDynamicSharedMemorySize, ATT_SMEM);

    // #1 fused preprocessing: msum + weight transposes + bias concat + LN1
    preproc_kernel<<<PRE_TOTAL, 256>>>(dis, cls, msum,
                                       wq, wk, wv, bq, bk, bv, wqkvT, bqkv,
                                       w1, w1T, w2, w2T,
                                       x, ln1g, ln1b, h1);
    // #2 fused QKV projection -> fp16 q/k/v
    gemm_mma<0><<<dim3(3 * DD / 128, NROWS / 128), 128, GEMM_SMEM>>>(
        h1, DD, wqkvT, bqkv, nullptr,
        nullptr, qb, kb, vb, nullptr, NROWS, 3 * DD, DD);
    // #3 flash attention (no-max softmax)
    attn_mma<<<dim3(HH, SS / 128, BB), 128, ATT_SMEM>>>(qb, kb, vb, msum, att);
    // #4 residual + LN2 -> f32 + fp16 (single-barrier)
    ln_kernel<<<NROWS, 256>>>(att, x, ln2g, ln2b, ln2o, ln2h);
    // #5 MLP up + GELU -> fp16
    gemm_mma<1><<<dim3(MLPD / 128, NROWS / 128), 128, GEMM_SMEM>>>(
        ln2h, DD, w1T, b1, nullptr,
        nullptr, nullptr, nullptr, nullptr, mlp, NROWS, MLPD, DD);
    // #6 MLP down + bias + f32 residual -> d_out
    gemm_mma<2><<<dim3(DD / 128, NROWS / 128), 128, GEMM_SMEM>>>(
        mlp, MLPD, w2T, b2, ln2o,
        out, nullptr, nullptr, nullptr, nullptr, NROWS, DD, MLPD);
}

// round 16
// speedup vs baseline: 1.0045x; 1.0045x over previous
#include <cuda_runtime.h>
#include <cuda_fp16.h>
#include <cstdint>
#include <cstddef>

// Problem constants
#define BB 2
#define SS 2048
#define DD 1024
#define HH 16
#define HDIM 64
#define MLPD 4096
#define NROWS (BB * SS)   // 4096

// ---------------------------------------------------------------------------
// Scratch (device globals) — all activations fp16
// ---------------------------------------------------------------------------
__device__ __half g_h1[NROWS * DD];
__device__ __half g_qb[NROWS * DD];
__device__ __half g_kb[NROWS * DD];
__device__ __half g_vb[NROWS * DD];
__device__ float  g_att[NROWS * DD];
__device__ float  g_ln2[NROWS * DD];
__device__ __half g_ln2h[NROWS * DD];
__device__ __half g_mlp[NROWS * MLPD];
__device__ __half g_msum[(size_t)BB * SS * SS];          // dis+cls, fp16
__device__ __half g_wqkvT[3 * DD * DD];
__device__ __half g_w1T[DD * MLPD];
__device__ __half g_w2T[DD * MLPD];
__device__ float  g_bqkv[3 * DD];

// ---------------------------------------------------------------------------
// PTX helpers
// ---------------------------------------------------------------------------
__device__ __forceinline__ uint32_t smem_u32(const void* p) {
    return (uint32_t)__cvta_generic_to_shared(p);
}
__device__ __forceinline__ void ldsm4(uint32_t* r, uint32_t a) {
    asm volatile("ldmatrix.sync.aligned.m8n8.x4.shared.b16 {%0,%1,%2,%3}, [%4];"
                 : "=r"(r[0]), "=r"(r[1]), "=r"(r[2]), "=r"(r[3]) : "r"(a));
}
__device__ __forceinline__ void ldsm4t(uint32_t* r, uint32_t a) {
    asm volatile("ldmatrix.sync.aligned.m8n8.x4.trans.shared.b16 {%0,%1,%2,%3}, [%4];"
                 : "=r"(r[0]), "=r"(r[1]), "=r"(r[2]), "=r"(r[3]) : "r"(a));
}
__device__ __forceinline__ void mma16816(float* c, const uint32_t* a, const uint32_t* b) {
    asm volatile("mma.sync.aligned.m16n8k16.row.col.f32.f16.f16.f32 "
                 "{%0,%1,%2,%3}, {%4,%5,%6,%7}, {%8,%9}, {%0,%1,%2,%3};"
                 : "+f"(c[0]), "+f"(c[1]), "+f"(c[2]), "+f"(c[3])
                 : "r"(a[0]), "r"(a[1]), "r"(a[2]), "r"(a[3]), "r"(b[0]), "r"(b[1]));
}
__device__ __forceinline__ void cp16(uint32_t d, const void* s) {
    asm volatile("cp.async.cg.shared.global [%0], [%1], 16;" :: "r"(d), "l"(s) : "memory");
}
__device__ __forceinline__ void cp_commit() {
    asm volatile("cp.async.commit_group;" ::: "memory");
}
template <int N>
__device__ __forceinline__ void cpwait() {
    asm volatile("cp.async.wait_group %0;" :: "n"(N) : "memory");
}
__device__ __forceinline__ uint32_t packhf(float lo, float hi) {
    uint32_t d;
    asm("cvt.rn.f16x2.f32 %0, %1, %2;" : "=r"(d) : "f"(hi), "f"(lo));
    return d;
}
__device__ __forceinline__ float gelu_exact(float x) {
    return 0.5f * x * (1.0f + erff(x * 0.70710678118654752f));
}

// ---------------------------------------------------------------------------
// Block LayerNorm body (best-measured version: 256 threads, one row per block)
// ---------------------------------------------------------------------------
__device__ __forceinline__ void ln_body(const float* __restrict__ in,
                                        const float* __restrict__ res,
                                        const float* __restrict__ gam,
                                        const float* __restrict__ bet,
                                        float* __restrict__ outf, __half* __restrict__ oh,
                                        int row, int t)
{
    float4 v = ((const float4*)(in + (size_t)row * DD))[t];
    if (res) {
        float4 r = ((const float4*)(res + (size_t)row * DD))[t];
        v.x += r.x; v.y += r.y; v.z += r.z; v.w += r.w;
    }
    float s  = v.x + v.y + v.z + v.w;
    float sq = v.x*v.x + v.y*v.y + v.z*v.z + v.w*v.w;

    __shared__ float red[20];
    #pragma unroll
    for (int o = 16; o; o >>= 1) {
        s  += __shfl_xor_sync(0xffffffffu, s,  o);
        sq += __shfl_xor_sync(0xffffffffu, sq, o);
    }
    int w = t >> 5, lane = t & 31;
    if (lane == 0) { red[w] = s; red[8 + w] = sq; }
    __syncthreads();
    if (w == 0) {
        float a  = (lane < 8) ? red[lane]     : 0.f;
        float b2 = (lane < 8) ? red[8 + lane] : 0.f;
        #pragma unroll
        for (int o = 4; o; o >>= 1) {
            a  += __shfl_xor_sync(0xffffffffu, a,  o);
            b2 += __shfl_xor_sync(0xffffffffu, b2, o);
        }
        if (lane == 0) { red[16] = a; red[17] = b2; }
    }
    __syncthreads();
    float mu  = red[16] * (1.0f / DD);
    float var = red[17] * (1.0f / DD) - mu * mu;
    float rn  = rsqrtf(var + 1e-5f);

    float4 g = ((const float4*)gam)[t];
    float4 b = ((const float4*)bet)[t];
    float o0 = (v.x - mu) * rn * g.x + b.x;
    float o1 = (v.y - mu) * rn * g.y + b.y;
    float o2 = (v.z - mu) * rn * g.z + b.z;
    float o3 = (v.w - mu) * rn * g.w + b.w;

    size_t base = (size_t)row * DD + t * 4;
    if (outf) *(float4*)(outf + base) = make_float4(o0, o1, o2, o3);
    *(__half2*)(oh + base)     = __floats2half2_rn(o0, o1);
    *(__half2*)(oh + base + 2) = __floats2half2_rn(o2, o3);
}

// LN2: residual + LN -> f32 + fp16 (one row per 256-thread block)
__global__ void ln_kernel(const float* __restrict__ in, const float* __restrict__ res,
                          const float* __restrict__ gam, const float* __restrict__ bet,
                          float* __restrict__ outf, __half* __restrict__ oh)
{
    ln_body(in, res, gam, bet, outf, oh, blockIdx.x, threadIdx.x);
}

// ---------------------------------------------------------------------------
// Fused preprocessing: one launch, block-range dispatch.
//   [0,      8192) : msum = fp16(dis + cls)
//   [8192,  11264) : wq/wk/wv transpose->fp16 + bias concat
//   [11264, 15360) : w1 transpose
//   [15360, 19456) : w2 transpose
//   [19456, 23552) : LN1 (block per row)
// ---------------------------------------------------------------------------
#define PRE_MSUM_END   8192
#define PRE_QKV_END    11264
#define PRE_W1_END     15360
#define PRE_W2_END     19456
#define PRE_TOTAL      23552

__device__ __forceinline__ void ttrans_body(const float* __restrict__ W,
                                            __half* __restrict__ o,
                                            int K, int N, int bx, int by,
                                            int tx, int ty)
{
    __shared__ float tile[32][33];
    int n0 = bx * 32, k0 = by * 32;
    #pragma unroll
    for (int i = 0; i < 32; i += 8)
        tile[ty + i][tx] = W[(size_t)(k0 + ty + i) * N + n0 + tx];
    __syncthreads();
    #pragma unroll
    for (int i = 0; i < 32; i += 8)
        o[(size_t)(n0 + ty + i) * K + k0 + tx] = __float2half_rn(tile[tx][ty + i]);
}

__global__ void preproc_kernel(
    const float* __restrict__ dis, const float* __restrict__ cls,
    __half* __restrict__ msum,
    const float* __restrict__ wq, const float* __restrict__ wk,
    const float* __restrict__ wv,
    const float* __restrict__ bq, const float* __restrict__ bk,
    const float* __restrict__ bv,
    __half* __restrict__ wqkvT, float* __restrict__ bqkv,
    const float* __restrict__ w1, __half* __restrict__ w1T,
    const float* __restrict__ w2, __half* __restrict__ w2T,
    const float* __restrict__ x,
    const float* __restrict__ ln1g, const float* __restrict__ ln1b,
    __half* __restrict__ h1)
{
    int bid = blockIdx.x;
    int t = threadIdx.x;
    int tx = t & 31, ty = t >> 5;

    if (bid < PRE_MSUM_END) {
        size_t i = ((size_t)bid * 256 + t) * 4;
        float4 d = *(const float4*)(dis + i);
        float4 c = *(const float4*)(cls + i);
        *(__half2*)(msum + i)     = __floats2half2_rn(d.x + c.x, d.y + c.y);
        *(__half2*)(msum + i + 2) = __floats2half2_rn(d.z + c.z, d.w + c.w);
    } else if (bid < PRE_QKV_END) {
        int r = bid - PRE_MSUM_END;
        int z = r >> 10;           // 0..2
        r &= 1023;
        int bx = r & 31, by = r >> 5;
        const float* W = (z == 0) ? wq : (z == 1) ? wk : wv;
        ttrans_body(W, wqkvT + (size_t)z * DD * DD, DD, DD, bx, by, tx, ty);
        if (bx == 0 && by == 0) {
            const float* bsrc = (z == 0) ? bq : (z == 1) ? bk : bv;
            #pragma unroll
            for (int i = t; i < DD; i += 256) bqkv[z * DD + i] = bsrc[i];
        }
    } else if (bid < PRE_W1_END) {
        int r = bid - PRE_QKV_END;
        int bx = r & 127, by = r >> 7;     // grid (128, 32)
        ttrans_body(w1, w1T, DD, MLPD, bx, by, tx, ty);
    } else if (bid < PRE_W2_END) {
        int r = bid - PRE_W1_END;
        int bx = r & 31, by = r >> 5;      // grid (32, 128)
        ttrans_body(w2, w2T, MLPD, DD, bx, by, tx, ty);
    } else {
        int row = bid - PRE_W2_END;
        ln_body(x, nullptr, ln1g, ln1b, nullptr, h1, row, t);
    }
}

// ---------------------------------------------------------------------------
// fp16 mma.sync GEMM, 128 threads, 4 warps of 64x64 warp tiles.
// Tile 128x128 x BK=64, 3-stage cp.async, one barrier per chunk, 2 CTAs/SM.
// EPI: 0 = bias -> fp16 routed to q/k/v;  1 = bias+GELU -> fp16;
//      2 = bias + f32 residual -> f32
// ---------------------------------------------------------------------------
#define GTILE 18432            // 128 rows * 144B
#define GSTAGE (2 * GTILE)     // A, B
#define GEMM_SMEM (3 * GSTAGE) // 110592

template <int EPI>
__global__ void __launch_bounds__(128, 2) gemm_mma(
    const __half* __restrict__ A, int lda,
    const __half* __restrict__ B,
    const float* __restrict__ bias, const float* __restrict__ addsrc,
    float* __restrict__ Cf,
    __half* __restrict__ Cbq, __half* __restrict__ Cbk, __half* __restrict__ Cbv,
    __half* __restrict__ Ch,
    int M, int N, int K)
{
    extern __shared__ __align__(128) char smem[];
    uint32_t sb = smem_u32(smem);
    int t = threadIdx.x, lane = t & 31, wid = t >> 5;
    int wm = wid & 1, wn = wid >> 1;          // 2x2 warps, warp tile 64x64
    int brow = blockIdx.y * 128, bcol = blockIdx.x * 128;

    const __half* Ab = A + (size_t)brow * lda;
    const __half* Bb = B + (size_t)bcol * K;
    const int NC = K / 64;

    auto load_chunk = [&](int c, int stg) {
        int k0 = c * 64;
        uint32_t sbase = sb + stg * GSTAGE;
        #pragma unroll
        for (int i = 0; i < 16; i++) {
            int cid = t + i * 128;
            int tile = cid >> 10;             // 0=A 1=B
            int w = cid & 1023;
            int row = w >> 3, g = w & 7;
            const __half* src = (tile ? Bb + (size_t)row * K : Ab + (size_t)row * lda)
                                + k0 + g * 8;
            cp16(sbase + tile * GTILE + row * 144 + g * 16, src);
        }
    };

    float acc[4][8][4];
    #pragma unroll
    for (int i = 0; i < 4; i++)
        #pragma unroll
        for (int j = 0; j < 8; j++)
            #pragma unroll
            for (int q = 0; q < 4; q++) acc[i][j][q] = 0.f;

    load_chunk(0, 0); cp_commit();
    load_chunk(1, 1); cp_commit();

    for (int c = 0; c < NC; c++) {
        if (c + 1 < NC) cpwait<1>(); else cpwait<0>();
        __syncthreads();
        if (c + 2 < NC) { load_chunk(c + 2, (c + 2) % 3); cp_commit(); }

        uint32_t stg = sb + (c % 3) * GSTAGE;
        #pragma unroll
        for (int hb = 0; hb < 2; hb++) {
            uint32_t kb2 = hb * 64;
            uint32_t ah[8][4];                // 4 row-groups x 2 ks
            #pragma unroll
            for (int it = 0; it < 4; it++)
                #pragma unroll
                for (int ks = 0; ks < 2; ks++) {
                    int row = wm * 64 + it * 16 + (lane & 15);
                    ldsm4(ah[it * 2 + ks],
                          stg + (uint32_t)(row * 144) + kb2 + ks * 32 + (lane >> 4) * 16);
                }
            #pragma unroll
            for (int g2 = 0; g2 < 2; g2++) {
                uint32_t bq[4][4];
                #pragma unroll
                for (int n4 = 0; n4 < 4; n4++) {
                    int n = wn * 64 + (g2 * 4 + n4) * 8 + (lane & 7);
                    ldsm4(bq[n4], stg + GTILE + (uint32_t)(n * 144) + kb2 + (lane >> 3) * 16);
                }
                #pragma unroll
                for (int it = 0; it < 4; it++)
                    #pragma unroll
                    for (int ks = 0; ks < 2; ks++)
                        #pragma unroll
                        for (int n4 = 0; n4 < 4; n4++)
                            mma16816(acc[it][g2 * 4 + n4],
                                     ah[it * 2 + ks], &bq[n4][ks * 2]);
            }
        }
    }

    // ---- epilogue ----
    __half* Cb = Cbq;
    int colbase = bcol;
    if (EPI == 0) {
        int which = bcol >> 10;
        Cb = (which == 0) ? Cbq : (which == 1) ? Cbk : Cbv;
        colbase = bcol & 1023;
    }
    const int OSTR = (EPI == 0) ? DD : N;

    #pragma unroll
    for (int it = 0; it < 4; it++) {
        int r0 = brow + wm * 64 + it * 16 + (lane >> 2);
        #pragma unroll
        for (int nt = 0; nt < 8; nt++) {
            int cofs = wn * 64 + nt * 8 + 2 * (lane & 3);
            int gb = bcol + cofs;
            int col = colbase + cofs;
            float b0 = bias[gb], b1 = bias[gb + 1];
            float v00 = acc[it][nt][0] + b0, v01 = acc[it][nt][1] + b1;
            float v10 = acc[it][nt][2] + b0, v11 = acc[it][nt][3] + b1;
            if (EPI == 0) {
                *(uint32_t*)(Cb + (size_t)r0 * OSTR + col)       = packhf(v00, v01);
                *(uint32_t*)(Cb + (size_t)(r0 + 8) * OSTR + col) = packhf(v10, v11);
            } else if (EPI == 1) {
                v00 = gelu_exact(v00); v01 = gelu_exact(v01);
                v10 = gelu_exact(v10); v11 = gelu_exact(v11);
                *(uint32_t*)(Ch + (size_t)r0 * OSTR + col)       = packhf(v00, v01);
                *(uint32_t*)(Ch + (size_t)(r0 + 8) * OSTR + col) = packhf(v10, v11);
            } else {
                const float* a0 = addsrc + (size_t)r0 * OSTR + col;
                const float* a1 = addsrc + (size_t)(r0 + 8) * OSTR + col;
                *(float2*)(Cf + (size_t)r0 * OSTR + col)       = make_float2(v00 + a0[0], v01 + a0[1]);
                *(float2*)(Cf + (size_t)(r0 + 8) * OSTR + col) = make_float2(v10 + a1[0], v11 + a1[1]);
            }
        }
    }
}

// ---------------------------------------------------------------------------
// Flash attention WITHOUT online max (bounded scores). fp16 mma.sync,
// 128 threads / 4 warps x 32 q-rows, 3-stage K/V cp.async, fp16 fused mask.
// ---------------------------------------------------------------------------
#define ATT_Q 18432            // 128 x 144
#define ATT_KV 9216            // 64 x 144
#define ATT_SMEM (ATT_Q + 3 * 2 * ATT_KV)   // 73728

__global__ void __launch_bounds__(128, 2) attn_mma(
    const __half* __restrict__ q, const __half* __restrict__ k,
    const __half* __restrict__ v,
    const __half* __restrict__ msum,
    float* __restrict__ out)
{
    extern __shared__ __align__(128) char sm[];
    uint32_t sb = smem_u32(sm);

    int h = blockIdx.x, qi = blockIdx.y, b = blockIdx.z;
    int t = threadIdx.x, lane = t & 31, wid = t >> 5;
    int wr = wid * 32;          // warp owns rows wr..wr+31 (2 groups of 16)

    size_t base = (size_t)b * (SS * DD) + (size_t)h * (SS * HDIM);
    const __half* Qg = q + base + (size_t)qi * 128 * HDIM;
    const __half* Kg = k + base;
    const __half* Vg = v + base;

    // load Q tile (128 x 64 fp16)
    #pragma unroll
    for (int i = 0; i < 8; i++) {
        int cid = t + i * 128;
        int row = cid >> 3, g = cid & 7;
        *(uint4*)(sm + row * 144 + g * 16) = *(const uint4*)(Qg + row * 64 + g * 8);
    }

    auto load_kv = [&](int kb, int st) {
        uint32_t kbase = sb + ATT_Q + st * 2 * ATT_KV;
        #pragma unroll
        for (int i = 0; i < 8; i++) {
            int cid = t + i * 128;
            int tile = cid >> 9;              // 0=K 1=V
            int w2 = cid & 511;
            int row = w2 >> 3, g = w2 & 7;
            const __half* src = (tile ? Vg : Kg) + (size_t)(kb * 64 + row) * 64 + g * 8;
            cp16(kbase + tile * ATT_KV + row * 144 + g * 16, src);
        }
    };

    load_kv(0, 0); cp_commit();
    load_kv(1, 1); cp_commit();
    __syncthreads();   // Q visible

    uint32_t qf[2][4][4];
    #pragma unroll
    for (int rg = 0; rg < 2; rg++)
        #pragma unroll
        for (int kt = 0; kt < 4; kt++) {
            int row = wr + rg * 16 + (lane & 15);
            ldsm4(qf[rg][kt], sb + (uint32_t)(row * 144 + kt * 32 + (lane >> 4) * 16));
        }

    float o[2][8][4];
    #pragma unroll
    for (int rg = 0; rg < 2; rg++)
        #pragma unroll
        for (int nt = 0; nt < 8; nt++)
            #pragma unroll
            for (int j = 0; j < 4; j++) o[rg][nt][j] = 0.f;
    float lpart[2][2] = {{0.f, 0.f}, {0.f, 0.f}};   // per-lane partial row sums

    int r0 = qi * 128 + wr + (lane >> 2);
    const __half* msr = msum + ((size_t)b * SS + r0) * SS;
    const int NKB = SS / 64;

    for (int kb = 0; kb < NKB; kb++) {
        if (kb + 1 < NKB) cpwait<1>(); else cpwait<0>();
        __syncthreads();
        if (kb + 2 < NKB) { load_kv(kb + 2, (kb + 2) % 3); cp_commit(); }

        uint32_t sbK = sb + ATT_Q + (kb % 3) * 2 * ATT_KV;
        uint32_t sbV = sbK + ATT_KV;

        // QK^T for both row groups; K frags loaded once
        float s[2][8][4];
        #pragma unroll
        for (int rg = 0; rg < 2; rg++)
            #pragma unroll
            for (int nt = 0; nt < 8; nt++)
                s[rg][nt][0] = s[rg][nt][1] = s[rg][nt][2] = s[rg][nt][3] = 0.f;
        #pragma unroll
        for (int half_ = 0; half_ < 2; half_++) {
            uint32_t kfr[4][8];
            #pragma unroll
            for (int n4 = 0; n4 < 4; n4++) {
                int tok = (half_ * 4 + n4) * 8 + (lane & 7);
                ldsm4(kfr[n4],     sbK + (uint32_t)(tok * 144 + (lane >> 3) * 16));
                ldsm4(kfr[n4] + 4, sbK + (uint32_t)(tok * 144 + 64 + (lane >> 3) * 16));
            }
            #pragma unroll
            for (int kt = 0; kt < 4; kt++)
                #pragma unroll
                for (int n4 = 0; n4 < 4; n4++)
                    #pragma unroll
                    for (int rg = 0; rg < 2; rg++)
                        mma16816(s[rg][half_ * 4 + n4], qf[rg][kt], &kfr[n4][kt * 2]);
        }

        // scale + mask + exp (no max subtraction; bounded scores)
        int cbase = kb * 64 + 2 * (lane & 3);
        #pragma unroll
        for (int rg = 0; rg < 2; rg++) {
            const __half* mr = msr + (size_t)(rg * 16) * SS;
            #pragma unroll
            for (int nt = 0; nt < 8; nt++) {
                int c = cbase + nt * 8;
                float2 m0 = __half22float2(*(const __half2*)(mr + c));
                float2 m1 = __half22float2(*(const __half2*)(mr + 8 * SS + c));
                s[rg][nt][0] = __expf(s[rg][nt][0] * 0.125f + m0.x);
                s[rg][nt][1] = __expf(s[rg][nt][1] * 0.125f + m0.y);
                s[rg][nt][2] = __expf(s[rg][nt][2] * 0.125f + m1.x);
                s[rg][nt][3] = __expf(s[rg][nt][3] * 0.125f + m1.y);
                lpart[rg][0] += s[rg][nt][0] + s[rg][nt][1];
                lpart[rg][1] += s[rg][nt][2] + s[rg][nt][3];
            }
        }

        // pack P -> A frags (fp16), per row group
        uint32_t pf[2][4][4];
        #pragma unroll
        for (int rg = 0; rg < 2; rg++)
            #pragma unroll
            for (int kt2 = 0; kt2 < 4; kt2++) {
                int j0 = 2 * kt2, j1 = 2 * kt2 + 1;
                pf[rg][kt2][0] = packhf(s[rg][j0][0], s[rg][j0][1]);
                pf[rg][kt2][1] = packhf(s[rg][j0][2], s[rg][j0][3]);
                pf[rg][kt2][2] = packhf(s[rg][j1][0], s[rg][j1][1]);
                pf[rg][kt2][3] = packhf(s[rg][j1][2], s[rg][j1][3]);
            }

        // P @ V — V frags loaded once, used by both row groups; o never rescaled
        #pragma unroll
        for (int kt2 = 0; kt2 < 4; kt2++) {
            #pragma unroll
            for (int ntp = 0; ntp < 4; ntp++) {
                uint32_t vf[4];
                int tok = kt2 * 16 + (lane & 15);
                int hd = (2 * ntp + (lane >> 4)) * 8;
                ldsm4t(vf, sbV + (uint32_t)(tok * 144 + hd * 2));
                #pragma unroll
                for (int rg = 0; rg < 2; rg++) {
                    mma16816(o[rg][2 * ntp],     pf[rg][kt2], &vf[0]);
                    mma16816(o[rg][2 * ntp + 1], pf[rg][kt2], &vf[2]);
                }
            }
        }
    }

    // final l reduction (once): 4 lanes per row share quads
    float* Og = out + base + (size_t)qi * 128 * HDIM;
    #pragma unroll
    for (int rg = 0; rg < 2; rg++) {
        float l0 = lpart[rg][0], l1 = lpart[rg][1];
        l0 += __shfl_xor_sync(0xffffffffu, l0, 1);
        l0 += __shfl_xor_sync(0xffffffffu, l0, 2);
        l1 += __shfl_xor_sync(0xffffffffu, l1, 1);
        l1 += __shfl_xor_sync(0xffffffffu, l1, 2);
        float inv0 = 1.0f / l0, inv1 = 1.0f / l1;
        int lr = wr + rg * 16 + (lane >> 2);
        #pragma unroll
        for (int nt = 0; nt < 8; nt++) {
            int col = nt * 8 + 2 * (lane & 3);
            *(float2*)(Og + (size_t)lr * 64 + col) =
                make_float2(o[rg][nt][0] * inv0, o[rg][nt][1] * inv0);
            *(float2*)(Og + (size_t)(lr + 8) * 64 + col) =
                make_float2(o[rg][nt][2] * inv1, o[rg][nt][3] * inv1);
        }
    }
}

// ---------------------------------------------------------------------------
// Launch: 6 kernels total
// ---------------------------------------------------------------------------
extern "C" void kernel_launch(void* const* d_in, const int* in_sizes, int n_in,
                              void* d_out, int out_size)
{
    const float* x     = (const float*)d_in[0];
    const float* dis   = (const float*)d_in[1];
    const float* cls   = (const float*)d_in[2];
    const float* wq    = (const float*)d_in[3];
    const float* bq    = (const float*)d_in[4];
    const float* wk    = (const float*)d_in[5];
    const float* bk    = (const float*)d_in[6];
    const float* wv    = (const float*)d_in[7];
    const float* bv    = (const float*)d_in[8];
    const float* ln1g  = (const float*)d_in[9];
    const float* ln1b  = (const float*)d_in[10];
    const float* ln2g  = (const float*)d_in[11];
    const float* ln2b  = (const float*)d_in[12];
    const float* w1    = (const float*)d_in[13];
    const float* b1    = (const float*)d_in[14];
    const float* w2    = (const float*)d_in[15];
    const float* b2    = (const float*)d_in[16];
    float* out = (float*)d_out;

    __half *h1, *ln2h, *mlp, *qb, *kb, *vb, *wqkvT, *w1T, *w2T, *msum;
    float *att, *ln2o, *bqkv;
    cudaGetSymbolAddress((void**)&h1,    g_h1);
    cudaGetSymbolAddress((void**)&ln2h,  g_ln2h);
    cudaGetSymbolAddress((void**)&mlp,   g_mlp);
    cudaGetSymbolAddress((void**)&wqkvT, g_wqkvT);
    cudaGetSymbolAddress((void**)&w1T,   g_w1T);
    cudaGetSymbolAddress((void**)&w2T,   g_w2T);
    cudaGetSymbolAddress((void**)&qb,    g_qb);
    cudaGetSymbolAddress((void**)&kb,    g_kb);
    cudaGetSymbolAddress((void**)&vb,    g_vb);
    cudaGetSymbolAddress((void**)&att,   g_att);
    cudaGetSymbolAddress((void**)&ln2o,  g_ln2);
    cudaGetSymbolAddress((void**)&bqkv,  g_bqkv);
    cudaGetSymbolAddress((void**)&msum,  g_msum);

    cudaFuncSetAttribute(gemm_mma<0>, cudaFuncAttributeMaxDynamicSharedMemorySize, GEMM_SMEM);
    cudaFuncSetAttribute(gemm_mma<1>, cudaFuncAttributeMaxDynamicSharedMemorySize, GEMM_SMEM);
    cudaFuncSetAttribute(gemm_mma<2>, cudaFuncAttributeMaxDynamicSharedMemorySize, GEMM_SMEM);
    cudaFuncSetAttribute(attn_mma, cudaFuncAttributeMaxDynamicSharedMemorySize, ATT_SMEM);

    // #1 fused preprocessing: msum + weight transposes + bias concat + LN1
    preproc_kernel<<<PRE_TOTAL, 256>>>(dis, cls, msum,
                                       wq, wk, wv, bq, bk, bv, wqkvT, bqkv,
                                       w1, w1T, w2, w2T,
                                       x, ln1g, ln1b, h1);
    // #2 fused QKV projection -> fp16 q/k/v
    gemm_mma<0><<<dim3(3 * DD / 128, NROWS / 128), 128, GEMM_SMEM>>>(
        h1, DD, wqkvT, bqkv, nullptr,
        nullptr, qb, kb, vb, nullptr, NROWS, 3 * DD, DD);
    // #3 flash attention (no-max softmax)
    attn_mma<<<dim3(HH, SS / 128, BB), 128, ATT_SMEM>>>(qb, kb, vb, msum, att);
    // #4 residual + LN2 -> f32 + fp16
    ln_kernel<<<NROWS, 256>>>(att, x, ln2g, ln2b, ln2o, ln2h);
    // #5 MLP up + GELU -> fp16
    gemm_mma<1><<<dim3(MLPD / 128, NROWS / 128), 128, GEMM_SMEM>>>(
        ln2h, DD, w1T, b1, nullptr,
        nullptr, nullptr, nullptr, nullptr, mlp, NROWS, MLPD, DD);
    // #6 MLP down + bias + f32 residual -> d_out
    gemm_mma<2><<<dim3(DD / 128, NROWS / 128), 128, GEMM_SMEM>>>(
        mlp, MLPD, w2T, b2, ln2o,
        out, nullptr, nullptr, nullptr, nullptr, NROWS, DD, MLPD);
}